// round 1
// baseline (speedup 1.0000x reference)
#include <cuda_runtime.h>
#include <cuda_bf16.h>
#include <cstdint>

// Problem constants
#define BSZ 4
#define LSEQ 2048
#define DDIM 512
#define EDIM 1024
#define NST 16
#define KCONV 4
#define RRANK 32
#define NTOK (BSZ * LSEQ)          // 8192

// ---------------- scratch (device globals; no allocs allowed) ----------------
__device__ float g_nrm[NTOK * DDIM];        // 8192x512
__device__ float g_xz [NTOK * 2 * EDIM];    // 8192x2048
__device__ float g_xs [NTOK * EDIM];        // 8192x1024 (post conv+silu)
__device__ float g_dbl[NTOK * (RRANK + 2 * NST)]; // 8192x64
__device__ float g_dt [NTOK * EDIM];        // 8192x1024 (post softplus)
__device__ float g_y  [NTOK * EDIM];        // 8192x1024 (gated)

// ---------------- RMSNorm ----------------
__global__ void rmsnorm_kernel(const float* __restrict__ x,
                               const float* __restrict__ w,
                               float* __restrict__ out) {
    int row = blockIdx.x;                 // token
    int tid = threadIdx.x;                // 128 threads, 4 floats each
    const float4* xr = (const float4*)(x + (size_t)row * DDIM);
    float4 v = xr[tid];
    float ss = v.x * v.x + v.y * v.y + v.z * v.z + v.w * v.w;
    #pragma unroll
    for (int o = 16; o > 0; o >>= 1) ss += __shfl_xor_sync(0xffffffffu, ss, o);
    __shared__ float sred[4];
    if ((tid & 31) == 0) sred[tid >> 5] = ss;
    __syncthreads();
    float tot = sred[0] + sred[1] + sred[2] + sred[3];
    float scale = rsqrtf(tot * (1.0f / DDIM) + 1e-6f);
    float4 wv = ((const float4*)w)[tid];
    float4 o4;
    o4.x = v.x * scale * wv.x;
    o4.y = v.y * scale * wv.y;
    o4.z = v.z * scale * wv.z;
    o4.w = v.w * scale * wv.w;
    ((float4*)(out + (size_t)row * DDIM))[tid] = o4;
}

// ---------------- generic fp32 tiled GEMM: C = A(MxK) * B(KxN) [+epilogue] ----------------
// EPI: 0 = none, 1 = bias + softplus, 2 = add residual (same layout as C)
template <int BM, int BN, int BK, int TM, int TN, int EPI>
__global__ void __launch_bounds__(256)
gemm_f32(const float* __restrict__ A, int lda,
         const float* __restrict__ Bm, int ldb,
         float* __restrict__ C, int ldc,
         int M, int N, int K,
         const float* __restrict__ bias,
         const float* __restrict__ resid) {
    __shared__ float As[BK][BM];
    __shared__ float Bs[BK][BN];

    const int tid = threadIdx.x;
    const int tx = tid % (BN / TN);
    const int ty = tid / (BN / TN);
    const int rowBase = blockIdx.y * BM;
    const int colBase = blockIdx.x * BN;

    float acc[TM][TN];
    #pragma unroll
    for (int i = 0; i < TM; i++)
        #pragma unroll
        for (int j = 0; j < TN; j++) acc[i][j] = 0.0f;

    constexpr int A_VECS = BM * BK / 4;
    constexpr int B_VECS = BK * BN / 4;

    for (int k0 = 0; k0 < K; k0 += BK) {
        #pragma unroll
        for (int i = tid; i < A_VECS; i += 256) {
            int row = i / (BK / 4);
            int kq  = i % (BK / 4);
            float4 v = *(const float4*)&A[(size_t)(rowBase + row) * lda + k0 + kq * 4];
            As[kq * 4 + 0][row] = v.x;
            As[kq * 4 + 1][row] = v.y;
            As[kq * 4 + 2][row] = v.z;
            As[kq * 4 + 3][row] = v.w;
        }
        #pragma unroll
        for (int i = tid; i < B_VECS; i += 256) {
            int kr = i / (BN / 4);
            int nq = i % (BN / 4);
            *(float4*)&Bs[kr][nq * 4] =
                *(const float4*)&Bm[(size_t)(k0 + kr) * ldb + colBase + nq * 4];
        }
        __syncthreads();

        #pragma unroll
        for (int kk = 0; kk < BK; kk++) {
            float a[TM], b[TN];
            #pragma unroll
            for (int i4 = 0; i4 < TM / 4; i4++)
                *(float4*)&a[i4 * 4] = *(const float4*)&As[kk][ty * TM + i4 * 4];
            #pragma unroll
            for (int j4 = 0; j4 < TN / 4; j4++)
                *(float4*)&b[j4 * 4] = *(const float4*)&Bs[kk][tx * TN + j4 * 4];
            #pragma unroll
            for (int i = 0; i < TM; i++)
                #pragma unroll
                for (int j = 0; j < TN; j++)
                    acc[i][j] = fmaf(a[i], b[j], acc[i][j]);
        }
        __syncthreads();
    }

    // epilogue + store
    #pragma unroll
    for (int i = 0; i < TM; i++) {
        int row = rowBase + ty * TM + i;
        #pragma unroll
        for (int j4 = 0; j4 < TN / 4; j4++) {
            int col = colBase + tx * TN + j4 * 4;
            float4 r;
            float vv[4];
            #pragma unroll
            for (int q = 0; q < 4; q++) {
                float v = acc[i][j4 * 4 + q];
                if (EPI == 1) {
                    v += bias[col + q];
                    v = (v > 20.0f) ? v : log1pf(expf(v));
                } else if (EPI == 2) {
                    v += resid[(size_t)row * ldc + col + q];
                }
                vv[q] = v;
            }
            r.x = vv[0]; r.y = vv[1]; r.z = vv[2]; r.w = vv[3];
            *(float4*)&C[(size_t)row * ldc + col] = r;
        }
    }
}

// ---------------- causal depthwise conv (K=4) + SiLU ----------------
// input: xs half of g_xz (stride 2E), output g_xs (stride E)
__global__ void conv_silu_kernel(const float* __restrict__ xz,
                                 const float* __restrict__ conv_w,
                                 const float* __restrict__ conv_b,
                                 float* __restrict__ xs) {
    const int e  = blockIdx.x * blockDim.x + threadIdx.x;  // 0..E-1
    const int t0 = blockIdx.y * 16;
    const int b  = blockIdx.z;
    const float w0 = conv_w[e * 4 + 0];
    const float w1 = conv_w[e * 4 + 1];
    const float w2 = conv_w[e * 4 + 2];
    const float w3 = conv_w[e * 4 + 3];
    const float bb = conv_b[e];

    float v[19];
    #pragma unroll
    for (int i = 0; i < 19; i++) {
        int t = t0 - 3 + i;
        v[i] = (t >= 0) ? xz[((size_t)(b * LSEQ + t)) * (2 * EDIM) + e] : 0.0f;
    }
    #pragma unroll
    for (int j = 0; j < 16; j++) {
        float a = bb + w0 * v[j] + w1 * v[j + 1] + w2 * v[j + 2] + w3 * v[j + 3];
        float s = a / (1.0f + __expf(-a));          // silu
        xs[((size_t)(b * LSEQ + t0 + j)) * EDIM + e] = s;
    }
}

// ---------------- selective scan + D-skip + silu(z) gating ----------------
// one warp handles 2 channels e (16 lanes each = one state n per lane)
__global__ void scan_kernel(const float* __restrict__ dt,
                            const float* __restrict__ xs,
                            const float* __restrict__ dbl,
                            const float* __restrict__ xz,
                            const float* __restrict__ A_log,
                            const float* __restrict__ D_skip,
                            float* __restrict__ y) {
    const int b    = blockIdx.y;
    const int warp = threadIdx.x >> 5;        // 0..3
    const int lane = threadIdx.x & 31;
    const int half = lane >> 4;
    const int n    = lane & 15;
    const int e    = blockIdx.x * 8 + warp * 2 + half;

    const float Acoef = -__expf(A_log[e * NST + n]);
    const float dsk   = D_skip[e];

    const float* dtp  = dt  + (size_t)b * LSEQ * EDIM + e;
    const float* xsp  = xs  + (size_t)b * LSEQ * EDIM + e;
    const float* dblp = dbl + (size_t)b * LSEQ * 64;
    const float* zp   = xz  + (size_t)b * LSEQ * (2 * EDIM) + EDIM + e;
    float*       yp   = y   + (size_t)b * LSEQ * EDIM + e;

    float h = 0.0f;
    for (int t = 0; t < LSEQ; t++) {
        float dtv = dtp[t * EDIM];
        float xsv = xsp[t * EDIM];
        float Bv  = dblp[t * 64 + RRANK + n];
        float Cv  = dblp[t * 64 + RRANK + NST + n];
        float dA  = __expf(dtv * Acoef);
        h = fmaf(dA, h, dtv * xsv * Bv);
        float yc = h * Cv;
        yc += __shfl_xor_sync(0xffffffffu, yc, 8, 16);
        yc += __shfl_xor_sync(0xffffffffu, yc, 4, 16);
        yc += __shfl_xor_sync(0xffffffffu, yc, 2, 16);
        yc += __shfl_xor_sync(0xffffffffu, yc, 1, 16);
        if (n == 0) {
            float zv  = zp[t * (2 * EDIM)];
            float sig = 1.0f / (1.0f + __expf(-zv));
            yp[t * EDIM] = (yc + xsv * dsk) * (zv * sig);
        }
    }
}

// ---------------- launcher ----------------
extern "C" void kernel_launch(void* const* d_in, const int* in_sizes, int n_in,
                              void* d_out, int out_size) {
    const float* hidden = (const float*)d_in[0];
    const float* norm_w = (const float*)d_in[1];
    const float* W_in   = (const float*)d_in[2];
    const float* conv_w = (const float*)d_in[3];
    const float* conv_b = (const float*)d_in[4];
    const float* W_x    = (const float*)d_in[5];
    const float* W_dt   = (const float*)d_in[6];
    const float* b_dt   = (const float*)d_in[7];
    const float* A_log  = (const float*)d_in[8];
    const float* D_skip = (const float*)d_in[9];
    const float* W_out  = (const float*)d_in[10];
    float* out = (float*)d_out;

    float *p_nrm, *p_xz, *p_xs, *p_dbl, *p_dt, *p_y;
    cudaGetSymbolAddress((void**)&p_nrm, g_nrm);
    cudaGetSymbolAddress((void**)&p_xz,  g_xz);
    cudaGetSymbolAddress((void**)&p_xs,  g_xs);
    cudaGetSymbolAddress((void**)&p_dbl, g_dbl);
    cudaGetSymbolAddress((void**)&p_dt,  g_dt);
    cudaGetSymbolAddress((void**)&p_y,   g_y);

    // 1) RMSNorm
    rmsnorm_kernel<<<NTOK, 128>>>(hidden, norm_w, p_nrm);

    // 2) xz = nrm @ W_in : (8192x512)x(512x2048)
    gemm_f32<128, 128, 16, 8, 8, 0><<<dim3(2 * EDIM / 128, NTOK / 128), 256>>>(
        p_nrm, DDIM, W_in, 2 * EDIM, p_xz, 2 * EDIM,
        NTOK, 2 * EDIM, DDIM, nullptr, nullptr);

    // 3) causal depthwise conv + silu
    conv_silu_kernel<<<dim3(EDIM / 256, LSEQ / 16, BSZ), 256>>>(p_xz, conv_w, conv_b, p_xs);

    // 4) dbl = xs @ W_x : (8192x1024)x(1024x64)
    gemm_f32<64, 64, 16, 4, 4, 0><<<dim3(1, NTOK / 64), 256>>>(
        p_xs, EDIM, W_x, 64, p_dbl, 64,
        NTOK, 64, EDIM, nullptr, nullptr);

    // 5) dt = softplus(dbl[:, :32] @ W_dt + b_dt) : (8192x32)x(32x1024)
    gemm_f32<128, 128, 16, 8, 8, 1><<<dim3(EDIM / 128, NTOK / 128), 256>>>(
        p_dbl, 64, W_dt, EDIM, p_dt, EDIM,
        NTOK, EDIM, RRANK, b_dt, nullptr);

    // 6) selective scan + gate
    scan_kernel<<<dim3(EDIM / 8, BSZ), 128>>>(p_dt, p_xs, p_dbl, p_xz, A_log, D_skip, p_y);

    // 7) out = y @ W_out + hidden : (8192x1024)x(1024x512)
    gemm_f32<128, 128, 16, 8, 8, 2><<<dim3(DDIM / 128, NTOK / 128), 256>>>(
        p_y, EDIM, W_out, DDIM, out, DDIM,
        NTOK, DDIM, EDIM, nullptr, hidden);
}

// round 3
// speedup vs baseline: 1.2225x; 1.2225x over previous
#include <cuda_runtime.h>
#include <cuda_bf16.h>
#include <cstdint>

using bf16 = __nv_bfloat16;

// Problem constants
#define BSZ 4
#define LSEQ 2048
#define DDIM 512
#define EDIM 1024
#define NST 16
#define RRANK 32
#define NTOK (BSZ * LSEQ)          // 8192

// ---------------- scratch (device globals) ----------------
__device__ float g_xz [NTOK * 2 * EDIM];    // fp32 (conv + z-gate consumers)
__device__ float g_xs [NTOK * EDIM];        // fp32 (scan consumer)
__device__ float g_dbl[NTOK * 64];          // fp32 (scan consumer: B,C)
__device__ float g_dt [NTOK * EDIM];        // fp32 (scan consumer)
__device__ bf16  g_nrmb[NTOK * DDIM];       // GEMM A operands (bf16)
__device__ bf16  g_xsb [NTOK * EDIM];
__device__ bf16  g_dblb[NTOK * 64];
__device__ bf16  g_yb  [NTOK * EDIM];
__device__ bf16  g_winb [DDIM * 2 * EDIM];  // weights (bf16)
__device__ bf16  g_wxb  [EDIM * 64];
__device__ bf16  g_wdtb [RRANK * EDIM];
__device__ bf16  g_woutb[EDIM * DDIM];

// ---------------- PTX helpers ----------------
__device__ __forceinline__ uint32_t smem_u32(const void* p) {
    return (uint32_t)__cvta_generic_to_shared(p);
}
__device__ __forceinline__ void cp_async16(void* s, const void* g) {
    asm volatile("cp.async.cg.shared.global [%0], [%1], 16;\n"
                 :: "r"(smem_u32(s)), "l"(g));
}
__device__ __forceinline__ void cp_commit() { asm volatile("cp.async.commit_group;\n"); }
template <int N> __device__ __forceinline__ void cp_wait() {
    asm volatile("cp.async.wait_group %0;\n" :: "n"(N));
}
__device__ __forceinline__ void ldsm_x4(uint32_t& r0, uint32_t& r1, uint32_t& r2, uint32_t& r3,
                                        uint32_t a) {
    asm volatile("ldmatrix.sync.aligned.m8n8.x4.shared.b16 {%0,%1,%2,%3}, [%4];\n"
                 : "=r"(r0), "=r"(r1), "=r"(r2), "=r"(r3) : "r"(a));
}
__device__ __forceinline__ void ldsm_x4_t(uint32_t& r0, uint32_t& r1, uint32_t& r2, uint32_t& r3,
                                          uint32_t a) {
    asm volatile("ldmatrix.sync.aligned.m8n8.x4.trans.shared.b16 {%0,%1,%2,%3}, [%4];\n"
                 : "=r"(r0), "=r"(r1), "=r"(r2), "=r"(r3) : "r"(a));
}
__device__ __forceinline__ void mma_bf16(float& d0, float& d1, float& d2, float& d3,
                                         uint32_t a0, uint32_t a1, uint32_t a2, uint32_t a3,
                                         uint32_t b0, uint32_t b1) {
    asm volatile("mma.sync.aligned.m16n8k16.row.col.f32.bf16.bf16.f32 "
                 "{%0,%1,%2,%3}, {%4,%5,%6,%7}, {%8,%9}, {%0,%1,%2,%3};\n"
                 : "+f"(d0), "+f"(d1), "+f"(d2), "+f"(d3)
                 : "r"(a0), "r"(a1), "r"(a2), "r"(a3), "r"(b0), "r"(b1));
}

// ---------------- fp32 -> bf16 convert ----------------
__global__ void f2bf_kernel(const float* __restrict__ in, bf16* __restrict__ out, int n) {
    int i = blockIdx.x * blockDim.x + threadIdx.x;
    if (i * 4 < n) {
        float4 v = *(const float4*)(in + i * 4);
        bf16 o[4] = {__float2bfloat16(v.x), __float2bfloat16(v.y),
                     __float2bfloat16(v.z), __float2bfloat16(v.w)};
        *(uint64_t*)(out + i * 4) = *(uint64_t*)o;
    }
}

// ---------------- RMSNorm -> bf16 ----------------
__global__ void rmsnorm_kernel(const float* __restrict__ x,
                               const float* __restrict__ w,
                               bf16* __restrict__ out) {
    int row = blockIdx.x;
    int tid = threadIdx.x;                // 128 threads x 4 floats
    float4 v = ((const float4*)(x + (size_t)row * DDIM))[tid];
    float ss = v.x * v.x + v.y * v.y + v.z * v.z + v.w * v.w;
    #pragma unroll
    for (int o = 16; o > 0; o >>= 1) ss += __shfl_xor_sync(0xffffffffu, ss, o);
    __shared__ float sred[4];
    if ((tid & 31) == 0) sred[tid >> 5] = ss;
    __syncthreads();
    float tot = sred[0] + sred[1] + sred[2] + sred[3];
    float scale = rsqrtf(tot * (1.0f / DDIM) + 1e-6f);
    float4 wv = ((const float4*)w)[tid];
    bf16 o[4] = {__float2bfloat16(v.x * scale * wv.x),
                 __float2bfloat16(v.y * scale * wv.y),
                 __float2bfloat16(v.z * scale * wv.z),
                 __float2bfloat16(v.w * scale * wv.w)};
    *(uint64_t*)(out + (size_t)row * DDIM + tid * 4) = *(uint64_t*)o;
}

// ---------------- bf16 tensor-core GEMM ----------------
// C(MxN fp32) = A(MxK bf16, row-major) * B(KxN bf16, row-major)
// EPI: 0 none | 1 bias+softplus | 2 +resid | 3 also write bf16 copy C2
template <int BM, int BN, int WGM, int WGN, int EPI>
__global__ void __launch_bounds__(WGM * WGN * 32)
gemm_bf16(const bf16* __restrict__ A, int lda,
          const bf16* __restrict__ B, int ldb,
          float* __restrict__ C, int ldc,
          int M, int N, int K,
          const float* __restrict__ bias,
          const float* __restrict__ resid,
          bf16* __restrict__ C2) {
    constexpr int BK = 32;
    constexpr int NTHR = WGM * WGN * 32;
    constexpr int WM = BM / WGM;
    constexpr int WN = BN / WGN;
    constexpr int MT = WM / 16;
    constexpr int NT = WN / 8;
    static_assert(NT % 2 == 0, "NT even");

    __shared__ __align__(16) bf16 As[2][BM][BK + 8];
    __shared__ __align__(16) bf16 Bs[2][BK][BN + 8];

    const int tid = threadIdx.x;
    const int warp = tid >> 5, lane = tid & 31;
    const int wm = (warp % WGM) * WM;
    const int wn = (warp / WGM) * WN;
    const int rowBase = blockIdx.y * BM;
    const int colBase = blockIdx.x * BN;

    float acc[MT][NT][4];
    #pragma unroll
    for (int i = 0; i < MT; i++)
        #pragma unroll
        for (int j = 0; j < NT; j++)
            #pragma unroll
            for (int q = 0; q < 4; q++) acc[i][j][q] = 0.0f;

    constexpr int A_CHUNKS = BM * BK / 8;     // 16B chunks
    constexpr int B_CHUNKS = BK * BN / 8;

    auto load_tile = [&](int buf, int k0) {
        #pragma unroll
        for (int c = tid; c < A_CHUNKS; c += NTHR) {
            int row = c / (BK / 8);
            int col = (c % (BK / 8)) * 8;
            cp_async16(&As[buf][row][col],
                       &A[(size_t)(rowBase + row) * lda + k0 + col]);
        }
        #pragma unroll
        for (int c = tid; c < B_CHUNKS; c += NTHR) {
            int row = c / (BN / 8);
            int col = (c % (BN / 8)) * 8;
            cp_async16(&Bs[buf][row][col],
                       &B[(size_t)(k0 + row) * ldb + colBase + col]);
        }
        cp_commit();
    };

    const int KT = K / BK;
    load_tile(0, 0);

    const int arow = lane & 15, acol = (lane >> 4) * 8;
    const int bq = lane >> 3, bl = lane & 7;
    const int bk = (bq & 1) * 8 + bl, bn = (bq >> 1) * 8;

    for (int kt = 0; kt < KT; kt++) {
        const int buf = kt & 1;
        if (kt + 1 < KT) {
            load_tile(buf ^ 1, (kt + 1) * BK);
            cp_wait<1>();
        } else {
            cp_wait<0>();
        }
        __syncthreads();

        #pragma unroll
        for (int ks = 0; ks < 2; ks++) {
            uint32_t a[MT][4];
            #pragma unroll
            for (int mt = 0; mt < MT; mt++)
                ldsm_x4(a[mt][0], a[mt][1], a[mt][2], a[mt][3],
                        smem_u32(&As[buf][wm + mt * 16 + arow][ks * 16 + acol]));
            uint32_t b[NT][2];
            #pragma unroll
            for (int nt2 = 0; nt2 < NT / 2; nt2++) {
                uint32_t r0, r1, r2, r3;
                ldsm_x4_t(r0, r1, r2, r3,
                          smem_u32(&Bs[buf][ks * 16 + bk][wn + nt2 * 16 + bn]));
                b[2 * nt2][0] = r0; b[2 * nt2][1] = r1;
                b[2 * nt2 + 1][0] = r2; b[2 * nt2 + 1][1] = r3;
            }
            #pragma unroll
            for (int mt = 0; mt < MT; mt++)
                #pragma unroll
                for (int nt = 0; nt < NT; nt++)
                    mma_bf16(acc[mt][nt][0], acc[mt][nt][1], acc[mt][nt][2], acc[mt][nt][3],
                             a[mt][0], a[mt][1], a[mt][2], a[mt][3],
                             b[nt][0], b[nt][1]);
        }
        __syncthreads();
    }

    // epilogue
    #pragma unroll
    for (int mt = 0; mt < MT; mt++) {
        #pragma unroll
        for (int nt = 0; nt < NT; nt++) {
            int col = colBase + wn + nt * 8 + (lane & 3) * 2;
            #pragma unroll
            for (int h = 0; h < 2; h++) {
                int row = rowBase + wm + mt * 16 + (lane >> 2) + h * 8;
                float v0 = acc[mt][nt][2 * h + 0];
                float v1 = acc[mt][nt][2 * h + 1];
                if (EPI == 1) {
                    v0 += bias[col + 0];
                    v1 += bias[col + 1];
                    v0 = (v0 > 20.0f) ? v0 : log1pf(expf(v0));
                    v1 = (v1 > 20.0f) ? v1 : log1pf(expf(v1));
                } else if (EPI == 2) {
                    const float2 r = *(const float2*)&resid[(size_t)row * ldc + col];
                    v0 += r.x; v1 += r.y;
                }
                *(float2*)&C[(size_t)row * ldc + col] = make_float2(v0, v1);
                if (EPI == 3) {
                    bf16 o[2] = {__float2bfloat16(v0), __float2bfloat16(v1)};
                    *(uint32_t*)&C2[(size_t)row * ldc + col] = *(uint32_t*)o;
                }
            }
        }
    }
}

// ---------------- causal depthwise conv (K=4) + SiLU, dual fp32/bf16 output ----------------
__global__ void conv_silu_kernel(const float* __restrict__ xz,
                                 const float* __restrict__ conv_w,
                                 const float* __restrict__ conv_b,
                                 float* __restrict__ xs,
                                 bf16* __restrict__ xsb) {
    const int e  = blockIdx.x * blockDim.x + threadIdx.x;
    const int t0 = blockIdx.y * 16;
    const int b  = blockIdx.z;
    const float w0 = conv_w[e * 4 + 0];
    const float w1 = conv_w[e * 4 + 1];
    const float w2 = conv_w[e * 4 + 2];
    const float w3 = conv_w[e * 4 + 3];
    const float bb = conv_b[e];

    float v[19];
    #pragma unroll
    for (int i = 0; i < 19; i++) {
        int t = t0 - 3 + i;
        v[i] = (t >= 0) ? xz[((size_t)(b * LSEQ + t)) * (2 * EDIM) + e] : 0.0f;
    }
    #pragma unroll
    for (int j = 0; j < 16; j++) {
        float a = bb + w0 * v[j] + w1 * v[j + 1] + w2 * v[j + 2] + w3 * v[j + 3];
        float s = a / (1.0f + __expf(-a));
        size_t idx = ((size_t)(b * LSEQ + t0 + j)) * EDIM + e;
        xs[idx] = s;
        xsb[idx] = __float2bfloat16(s);
    }
}

// ---------------- selective scan + D-skip + silu(z) gating -> bf16 y ----------------
__global__ void scan_kernel(const float* __restrict__ dt,
                            const float* __restrict__ xs,
                            const float* __restrict__ dbl,
                            const float* __restrict__ xz,
                            const float* __restrict__ A_log,
                            const float* __restrict__ D_skip,
                            bf16* __restrict__ y) {
    const int b    = blockIdx.y;
    const int warp = threadIdx.x >> 5;
    const int lane = threadIdx.x & 31;
    const int half = lane >> 4;
    const int n    = lane & 15;
    const int e    = blockIdx.x * 8 + warp * 2 + half;

    const float Acoef = -__expf(A_log[e * NST + n]);
    const float dsk   = D_skip[e];

    const float* dtp  = dt  + (size_t)b * LSEQ * EDIM + e;
    const float* xsp  = xs  + (size_t)b * LSEQ * EDIM + e;
    const float* dblp = dbl + (size_t)b * LSEQ * 64;
    const float* zp   = xz  + (size_t)b * LSEQ * (2 * EDIM) + EDIM + e;
    bf16*        yp   = y   + (size_t)b * LSEQ * EDIM + e;

    float h = 0.0f;
    for (int t = 0; t < LSEQ; t++) {
        float dtv = dtp[t * EDIM];
        float xsv = xsp[t * EDIM];
        float Bv  = dblp[t * 64 + RRANK + n];
        float Cv  = dblp[t * 64 + RRANK + NST + n];
        float dA  = __expf(dtv * Acoef);
        h = fmaf(dA, h, dtv * xsv * Bv);
        float yc = h * Cv;
        yc += __shfl_xor_sync(0xffffffffu, yc, 8, 16);
        yc += __shfl_xor_sync(0xffffffffu, yc, 4, 16);
        yc += __shfl_xor_sync(0xffffffffu, yc, 2, 16);
        yc += __shfl_xor_sync(0xffffffffu, yc, 1, 16);
        if (n == 0) {
            float zv  = zp[t * (2 * EDIM)];
            float sig = 1.0f / (1.0f + __expf(-zv));
            yp[t * EDIM] = __float2bfloat16((yc + xsv * dsk) * (zv * sig));
        }
    }
}

// ---------------- launcher ----------------
extern "C" void kernel_launch(void* const* d_in, const int* in_sizes, int n_in,
                              void* d_out, int out_size) {
    const float* hidden = (const float*)d_in[0];
    const float* norm_w = (const float*)d_in[1];
    const float* W_in   = (const float*)d_in[2];
    const float* conv_w = (const float*)d_in[3];
    const float* conv_b = (const float*)d_in[4];
    const float* W_x    = (const float*)d_in[5];
    const float* W_dt   = (const float*)d_in[6];
    const float* b_dt   = (const float*)d_in[7];
    const float* A_log  = (const float*)d_in[8];
    const float* D_skip = (const float*)d_in[9];
    const float* W_out  = (const float*)d_in[10];
    float* out = (float*)d_out;

    float *p_xz, *p_xs, *p_dbl, *p_dt;
    bf16 *p_nrmb, *p_xsb, *p_dblb, *p_yb, *p_winb, *p_wxb, *p_wdtb, *p_woutb;
    cudaGetSymbolAddress((void**)&p_xz,   g_xz);
    cudaGetSymbolAddress((void**)&p_xs,   g_xs);
    cudaGetSymbolAddress((void**)&p_dbl,  g_dbl);
    cudaGetSymbolAddress((void**)&p_dt,   g_dt);
    cudaGetSymbolAddress((void**)&p_nrmb, g_nrmb);
    cudaGetSymbolAddress((void**)&p_xsb,  g_xsb);
    cudaGetSymbolAddress((void**)&p_dblb, g_dblb);
    cudaGetSymbolAddress((void**)&p_yb,   g_yb);
    cudaGetSymbolAddress((void**)&p_winb, g_winb);
    cudaGetSymbolAddress((void**)&p_wxb,  g_wxb);
    cudaGetSymbolAddress((void**)&p_wdtb, g_wdtb);
    cudaGetSymbolAddress((void**)&p_woutb, g_woutb);

    // 0) weight conversion to bf16
    f2bf_kernel<<<(DDIM * 2 * EDIM / 4 + 255) / 256, 256>>>(W_in,  p_winb,  DDIM * 2 * EDIM);
    f2bf_kernel<<<(EDIM * 64 / 4 + 255) / 256, 256>>>(W_x,   p_wxb,   EDIM * 64);
    f2bf_kernel<<<(RRANK * EDIM / 4 + 255) / 256, 256>>>(W_dt, p_wdtb, RRANK * EDIM);
    f2bf_kernel<<<(EDIM * DDIM / 4 + 255) / 256, 256>>>(W_out, p_woutb, EDIM * DDIM);

    // 1) RMSNorm -> bf16
    rmsnorm_kernel<<<NTOK, 128>>>(hidden, norm_w, p_nrmb);

    // 2) xz = nrm @ W_in : (8192x512)x(512x2048) -> fp32
    gemm_bf16<128, 128, 2, 4, 0><<<dim3(2 * EDIM / 128, NTOK / 128), 256>>>(
        p_nrmb, DDIM, p_winb, 2 * EDIM, p_xz, 2 * EDIM,
        NTOK, 2 * EDIM, DDIM, nullptr, nullptr, nullptr);

    // 3) conv + silu -> fp32 + bf16
    conv_silu_kernel<<<dim3(EDIM / 256, LSEQ / 16, BSZ), 256>>>(p_xz, conv_w, conv_b, p_xs, p_xsb);

    // 4) dbl = xs @ W_x : (8192x1024)x(1024x64) -> fp32 + bf16
    gemm_bf16<128, 64, 4, 2, 3><<<dim3(1, NTOK / 128), 256>>>(
        p_xsb, EDIM, p_wxb, 64, p_dbl, 64,
        NTOK, 64, EDIM, nullptr, nullptr, p_dblb);

    // 5) dt = softplus(dbl[:, :32] @ W_dt + b_dt) : (8192x32)x(32x1024)
    gemm_bf16<128, 128, 2, 4, 1><<<dim3(EDIM / 128, NTOK / 128), 256>>>(
        p_dblb, 64, p_wdtb, EDIM, p_dt, EDIM,
        NTOK, EDIM, RRANK, b_dt, nullptr, nullptr);

    // 6) selective scan + gate -> bf16 y
    scan_kernel<<<dim3(EDIM / 8, BSZ), 128>>>(p_dt, p_xs, p_dbl, p_xz, A_log, D_skip, p_yb);

    // 7) out = y @ W_out + hidden : (8192x1024)x(1024x512) -> fp32
    gemm_bf16<128, 128, 2, 4, 2><<<dim3(DDIM / 128, NTOK / 128), 256>>>(
        p_yb, EDIM, p_woutb, DDIM, out, DDIM,
        NTOK, DDIM, EDIM, nullptr, hidden, nullptr);
}

// round 4
// speedup vs baseline: 3.3393x; 2.7316x over previous
#include <cuda_runtime.h>
#include <cuda_bf16.h>
#include <cstdint>

using bf16 = __nv_bfloat16;

// Problem constants
#define BSZ 4
#define LSEQ 2048
#define DDIM 512
#define EDIM 1024
#define NST 16
#define RRANK 32
#define NTOK (BSZ * LSEQ)          // 8192

// ---------------- scratch (device globals) ----------------
__device__ float g_xz [NTOK * 2 * EDIM];    // fp32 (conv + z-transpose source)
__device__ float g_xs [NTOK * EDIM];        // fp32 (transpose source)
__device__ float g_dbl[NTOK * 64];          // fp32 (scan: B,C)
__device__ float g_dt [NTOK * EDIM];        // fp32 (transpose source)
__device__ float g_dtT[NTOK * EDIM];        // [b][e][t]
__device__ float g_xsT[NTOK * EDIM];        // [b][e][t]
__device__ float g_zT [NTOK * EDIM];        // [b][e][t]
__device__ bf16  g_nrmb[NTOK * DDIM];       // GEMM A operands (bf16)
__device__ bf16  g_xsb [NTOK * EDIM];
__device__ bf16  g_dblb[NTOK * 64];
__device__ bf16  g_yb  [NTOK * EDIM];
__device__ bf16  g_winb [DDIM * 2 * EDIM];  // weights (bf16)
__device__ bf16  g_wxb  [EDIM * 64];
__device__ bf16  g_wdtb [RRANK * EDIM];
__device__ bf16  g_woutb[EDIM * DDIM];

// ---------------- PTX helpers ----------------
__device__ __forceinline__ uint32_t smem_u32(const void* p) {
    return (uint32_t)__cvta_generic_to_shared(p);
}
__device__ __forceinline__ void cp_async16(void* s, const void* g) {
    asm volatile("cp.async.cg.shared.global [%0], [%1], 16;\n"
                 :: "r"(smem_u32(s)), "l"(g));
}
__device__ __forceinline__ void cp_commit() { asm volatile("cp.async.commit_group;\n"); }
template <int N> __device__ __forceinline__ void cp_wait() {
    asm volatile("cp.async.wait_group %0;\n" :: "n"(N));
}
__device__ __forceinline__ void ldsm_x4(uint32_t& r0, uint32_t& r1, uint32_t& r2, uint32_t& r3,
                                        uint32_t a) {
    asm volatile("ldmatrix.sync.aligned.m8n8.x4.shared.b16 {%0,%1,%2,%3}, [%4];\n"
                 : "=r"(r0), "=r"(r1), "=r"(r2), "=r"(r3) : "r"(a));
}
__device__ __forceinline__ void ldsm_x4_t(uint32_t& r0, uint32_t& r1, uint32_t& r2, uint32_t& r3,
                                          uint32_t a) {
    asm volatile("ldmatrix.sync.aligned.m8n8.x4.trans.shared.b16 {%0,%1,%2,%3}, [%4];\n"
                 : "=r"(r0), "=r"(r1), "=r"(r2), "=r"(r3) : "r"(a));
}
__device__ __forceinline__ void mma_bf16(float& d0, float& d1, float& d2, float& d3,
                                         uint32_t a0, uint32_t a1, uint32_t a2, uint32_t a3,
                                         uint32_t b0, uint32_t b1) {
    asm volatile("mma.sync.aligned.m16n8k16.row.col.f32.bf16.bf16.f32 "
                 "{%0,%1,%2,%3}, {%4,%5,%6,%7}, {%8,%9}, {%0,%1,%2,%3};\n"
                 : "+f"(d0), "+f"(d1), "+f"(d2), "+f"(d3)
                 : "r"(a0), "r"(a1), "r"(a2), "r"(a3), "r"(b0), "r"(b1));
}

// ---------------- fp32 -> bf16 convert ----------------
__global__ void f2bf_kernel(const float* __restrict__ in, bf16* __restrict__ out, int n) {
    int i = blockIdx.x * blockDim.x + threadIdx.x;
    if (i * 4 < n) {
        float4 v = *(const float4*)(in + i * 4);
        bf16 o[4] = {__float2bfloat16(v.x), __float2bfloat16(v.y),
                     __float2bfloat16(v.z), __float2bfloat16(v.w)};
        *(uint64_t*)(out + i * 4) = *(uint64_t*)o;
    }
}

// ---------------- RMSNorm -> bf16 ----------------
__global__ void rmsnorm_kernel(const float* __restrict__ x,
                               const float* __restrict__ w,
                               bf16* __restrict__ out) {
    int row = blockIdx.x;
    int tid = threadIdx.x;                // 128 threads x 4 floats
    float4 v = ((const float4*)(x + (size_t)row * DDIM))[tid];
    float ss = v.x * v.x + v.y * v.y + v.z * v.z + v.w * v.w;
    #pragma unroll
    for (int o = 16; o > 0; o >>= 1) ss += __shfl_xor_sync(0xffffffffu, ss, o);
    __shared__ float sred[4];
    if ((tid & 31) == 0) sred[tid >> 5] = ss;
    __syncthreads();
    float tot = sred[0] + sred[1] + sred[2] + sred[3];
    float scale = rsqrtf(tot * (1.0f / DDIM) + 1e-6f);
    float4 wv = ((const float4*)w)[tid];
    bf16 o[4] = {__float2bfloat16(v.x * scale * wv.x),
                 __float2bfloat16(v.y * scale * wv.y),
                 __float2bfloat16(v.z * scale * wv.z),
                 __float2bfloat16(v.w * scale * wv.w)};
    *(uint64_t*)(out + (size_t)row * DDIM + tid * 4) = *(uint64_t*)o;
}

// ---------------- bf16 tensor-core GEMM ----------------
// C(MxN fp32) = A(MxK bf16, row-major) * B(KxN bf16, row-major)
// EPI: 0 none | 1 bias+softplus | 2 +resid | 3 also write bf16 copy C2
template <int BM, int BN, int WGM, int WGN, int EPI>
__global__ void __launch_bounds__(WGM * WGN * 32)
gemm_bf16(const bf16* __restrict__ A, int lda,
          const bf16* __restrict__ B, int ldb,
          float* __restrict__ C, int ldc,
          int M, int N, int K,
          const float* __restrict__ bias,
          const float* __restrict__ resid,
          bf16* __restrict__ C2) {
    constexpr int BK = 32;
    constexpr int NTHR = WGM * WGN * 32;
    constexpr int WM = BM / WGM;
    constexpr int WN = BN / WGN;
    constexpr int MT = WM / 16;
    constexpr int NT = WN / 8;
    static_assert(NT % 2 == 0, "NT even");

    __shared__ __align__(16) bf16 As[2][BM][BK + 8];
    __shared__ __align__(16) bf16 Bs[2][BK][BN + 8];

    const int tid = threadIdx.x;
    const int warp = tid >> 5, lane = tid & 31;
    const int wm = (warp % WGM) * WM;
    const int wn = (warp / WGM) * WN;
    const int rowBase = blockIdx.y * BM;
    const int colBase = blockIdx.x * BN;

    float acc[MT][NT][4];
    #pragma unroll
    for (int i = 0; i < MT; i++)
        #pragma unroll
        for (int j = 0; j < NT; j++)
            #pragma unroll
            for (int q = 0; q < 4; q++) acc[i][j][q] = 0.0f;

    constexpr int A_CHUNKS = BM * BK / 8;     // 16B chunks
    constexpr int B_CHUNKS = BK * BN / 8;

    auto load_tile = [&](int buf, int k0) {
        #pragma unroll
        for (int c = tid; c < A_CHUNKS; c += NTHR) {
            int row = c / (BK / 8);
            int col = (c % (BK / 8)) * 8;
            cp_async16(&As[buf][row][col],
                       &A[(size_t)(rowBase + row) * lda + k0 + col]);
        }
        #pragma unroll
        for (int c = tid; c < B_CHUNKS; c += NTHR) {
            int row = c / (BN / 8);
            int col = (c % (BN / 8)) * 8;
            cp_async16(&Bs[buf][row][col],
                       &B[(size_t)(k0 + row) * ldb + colBase + col]);
        }
        cp_commit();
    };

    const int KT = K / BK;
    load_tile(0, 0);

    const int arow = lane & 15, acol = (lane >> 4) * 8;
    const int bq = lane >> 3, bl = lane & 7;
    const int bk = (bq & 1) * 8 + bl, bn = (bq >> 1) * 8;

    for (int kt = 0; kt < KT; kt++) {
        const int buf = kt & 1;
        if (kt + 1 < KT) {
            load_tile(buf ^ 1, (kt + 1) * BK);
            cp_wait<1>();
        } else {
            cp_wait<0>();
        }
        __syncthreads();

        #pragma unroll
        for (int ks = 0; ks < 2; ks++) {
            uint32_t a[MT][4];
            #pragma unroll
            for (int mt = 0; mt < MT; mt++)
                ldsm_x4(a[mt][0], a[mt][1], a[mt][2], a[mt][3],
                        smem_u32(&As[buf][wm + mt * 16 + arow][ks * 16 + acol]));
            uint32_t b[NT][2];
            #pragma unroll
            for (int nt2 = 0; nt2 < NT / 2; nt2++) {
                uint32_t r0, r1, r2, r3;
                ldsm_x4_t(r0, r1, r2, r3,
                          smem_u32(&Bs[buf][ks * 16 + bk][wn + nt2 * 16 + bn]));
                b[2 * nt2][0] = r0; b[2 * nt2][1] = r1;
                b[2 * nt2 + 1][0] = r2; b[2 * nt2 + 1][1] = r3;
            }
            #pragma unroll
            for (int mt = 0; mt < MT; mt++)
                #pragma unroll
                for (int nt = 0; nt < NT; nt++)
                    mma_bf16(acc[mt][nt][0], acc[mt][nt][1], acc[mt][nt][2], acc[mt][nt][3],
                             a[mt][0], a[mt][1], a[mt][2], a[mt][3],
                             b[nt][0], b[nt][1]);
        }
        __syncthreads();
    }

    // epilogue
    #pragma unroll
    for (int mt = 0; mt < MT; mt++) {
        #pragma unroll
        for (int nt = 0; nt < NT; nt++) {
            int col = colBase + wn + nt * 8 + (lane & 3) * 2;
            #pragma unroll
            for (int h = 0; h < 2; h++) {
                int row = rowBase + wm + mt * 16 + (lane >> 2) + h * 8;
                float v0 = acc[mt][nt][2 * h + 0];
                float v1 = acc[mt][nt][2 * h + 1];
                if (EPI == 1) {
                    v0 += bias[col + 0];
                    v1 += bias[col + 1];
                    v0 = (v0 > 20.0f) ? v0 : log1pf(expf(v0));
                    v1 = (v1 > 20.0f) ? v1 : log1pf(expf(v1));
                } else if (EPI == 2) {
                    const float2 r = *(const float2*)&resid[(size_t)row * ldc + col];
                    v0 += r.x; v1 += r.y;
                }
                *(float2*)&C[(size_t)row * ldc + col] = make_float2(v0, v1);
                if (EPI == 3) {
                    bf16 o[2] = {__float2bfloat16(v0), __float2bfloat16(v1)};
                    *(uint32_t*)&C2[(size_t)row * ldc + col] = *(uint32_t*)o;
                }
            }
        }
    }
}

// ---------------- causal depthwise conv (K=4) + SiLU, fp32 + bf16 out ----------------
__global__ void conv_silu_kernel(const float* __restrict__ xz,
                                 const float* __restrict__ conv_w,
                                 const float* __restrict__ conv_b,
                                 float* __restrict__ xs,
                                 bf16* __restrict__ xsb) {
    const int e  = blockIdx.x * blockDim.x + threadIdx.x;
    const int t0 = blockIdx.y * 16;
    const int b  = blockIdx.z;
    const float w0 = conv_w[e * 4 + 0];
    const float w1 = conv_w[e * 4 + 1];
    const float w2 = conv_w[e * 4 + 2];
    const float w3 = conv_w[e * 4 + 3];
    const float bb = conv_b[e];

    float v[19];
    #pragma unroll
    for (int i = 0; i < 19; i++) {
        int t = t0 - 3 + i;
        v[i] = (t >= 0) ? xz[((size_t)(b * LSEQ + t)) * (2 * EDIM) + e] : 0.0f;
    }
    #pragma unroll
    for (int j = 0; j < 16; j++) {
        float a = bb + w0 * v[j] + w1 * v[j + 1] + w2 * v[j + 2] + w3 * v[j + 3];
        float s = a / (1.0f + __expf(-a));
        size_t idx = ((size_t)(b * LSEQ + t0 + j)) * EDIM + e;
        xs[idx] = s;
        xsb[idx] = __float2bfloat16(s);
    }
}

// ---------------- tiled transpose: out[b][c][t] = in[(b*L+t)*stride + off + c] ----------------
__global__ void transpose_kernel(const float* __restrict__ in, int stride, int off,
                                 float* __restrict__ out) {
    __shared__ float tile[32][33];
    const int b  = blockIdx.z;
    const int t0 = blockIdx.x * 32;
    const int c0 = blockIdx.y * 32;
    const int tx = threadIdx.x, ty = threadIdx.y;     // 32 x 8
    #pragma unroll
    for (int i = ty; i < 32; i += 8)
        tile[i][tx] = in[((size_t)(b * LSEQ + t0 + i)) * stride + off + c0 + tx];
    __syncthreads();
    #pragma unroll
    for (int i = ty; i < 32; i += 8)
        out[((size_t)b * EDIM + c0 + i) * LSEQ + t0 + tx] = tile[tx][i];
}

// ---------------- chunked parallel selective scan ----------------
// one warp per (b, e); lane = 64-step time chunk; 16 states in registers
#define CHUNK 64
__global__ void __launch_bounds__(256)
scan_kernel(const float* __restrict__ dtT,
            const float* __restrict__ xsT,
            const float* __restrict__ zT,
            const float* __restrict__ dbl,
            const float* __restrict__ A_log,
            const float* __restrict__ D_skip,
            bf16* __restrict__ y) {
    const int b    = blockIdx.y;
    const int warp = threadIdx.x >> 5;
    const int lane = threadIdx.x & 31;
    const int e    = blockIdx.x * 8 + warp;

    __shared__ bf16 ystage[8][LSEQ + 32];   // +32 padding slots for (t>>6) swizzle

    float Acoef[NST];
    #pragma unroll
    for (int n = 0; n < NST; n++) Acoef[n] = -__expf(A_log[e * NST + n]);
    const float dsk = D_skip[e];

    const float* dtp  = dtT + ((size_t)b * EDIM + e) * LSEQ;
    const float* xsp  = xsT + ((size_t)b * EDIM + e) * LSEQ;
    const float* zp   = zT  + ((size_t)b * EDIM + e) * LSEQ;
    const float* dblp = dbl + (size_t)b * LSEQ * 64;

    const int t0 = lane * CHUNK;

    // ---- pass 1: per-chunk affine summary (P, q) ----
    float P[NST], q[NST];
    #pragma unroll
    for (int n = 0; n < NST; n++) { P[n] = 1.0f; q[n] = 0.0f; }

    for (int s = 0; s < CHUNK; s++) {
        const int t = t0 + s;
        const float dtv = dtp[t];
        const float xsv = xsp[t];
        float Bv[NST];
        #pragma unroll
        for (int j = 0; j < 4; j++) {
            float4 tb = *(const float4*)&dblp[(size_t)t * 64 + RRANK + j * 4];
            Bv[j*4+0] = tb.x; Bv[j*4+1] = tb.y; Bv[j*4+2] = tb.z; Bv[j*4+3] = tb.w;
        }
        const float dx = dtv * xsv;
        #pragma unroll
        for (int n = 0; n < NST; n++) {
            float dA = __expf(dtv * Acoef[n]);
            q[n] = fmaf(dA, q[n], dx * Bv[n]);
            P[n] *= dA;
        }
    }

    // ---- warp inclusive scan of affine maps over lanes ----
    #pragma unroll
    for (int d = 1; d < 32; d <<= 1) {
        #pragma unroll
        for (int n = 0; n < NST; n++) {
            float Pp = __shfl_up_sync(0xffffffffu, P[n], d);
            float qp = __shfl_up_sync(0xffffffffu, q[n], d);
            if (lane >= d) {
                q[n] = fmaf(P[n], qp, q[n]);
                P[n] *= Pp;
            }
        }
    }
    // exclusive: h0 for this lane = inclusive q of lane-1
    float h[NST];
    #pragma unroll
    for (int n = 0; n < NST; n++) {
        float v = __shfl_up_sync(0xffffffffu, q[n], 1);
        h[n] = (lane == 0) ? 0.0f : v;
    }

    // ---- pass 2: replay with true h0, produce gated y ----
    for (int s = 0; s < CHUNK; s++) {
        const int t = t0 + s;
        const float dtv = dtp[t];
        const float xsv = xsp[t];
        float Bv[NST], Cv[NST];
        #pragma unroll
        for (int j = 0; j < 4; j++) {
            float4 tb = *(const float4*)&dblp[(size_t)t * 64 + RRANK + j * 4];
            float4 tc = *(const float4*)&dblp[(size_t)t * 64 + RRANK + NST + j * 4];
            Bv[j*4+0] = tb.x; Bv[j*4+1] = tb.y; Bv[j*4+2] = tb.z; Bv[j*4+3] = tb.w;
            Cv[j*4+0] = tc.x; Cv[j*4+1] = tc.y; Cv[j*4+2] = tc.z; Cv[j*4+3] = tc.w;
        }
        const float dx = dtv * xsv;
        float yacc0 = 0.0f, yacc1 = 0.0f;
        #pragma unroll
        for (int n = 0; n < NST; n += 2) {
            float dA0 = __expf(dtv * Acoef[n]);
            float dA1 = __expf(dtv * Acoef[n + 1]);
            h[n]     = fmaf(dA0, h[n],     dx * Bv[n]);
            h[n + 1] = fmaf(dA1, h[n + 1], dx * Bv[n + 1]);
            yacc0 = fmaf(h[n],     Cv[n],     yacc0);
            yacc1 = fmaf(h[n + 1], Cv[n + 1], yacc1);
        }
        const float zv  = zp[t];
        const float sig = 1.0f / (1.0f + __expf(-zv));
        const float out = ((yacc0 + yacc1) + xsv * dsk) * (zv * sig);
        ystage[warp][t + (t >> 6)] = __float2bfloat16(out);
    }
    __syncthreads();

    // ---- cooperative coalesced write: y[b*L+t][e0..e0+7] ----
    const int e0 = blockIdx.x * 8;
    for (int t = threadIdx.x; t < LSEQ; t += 256) {
        bf16 v[8];
        #pragma unroll
        for (int w = 0; w < 8; w++) v[w] = ystage[w][t + (t >> 6)];
        *(uint4*)&y[((size_t)(b * LSEQ + t)) * EDIM + e0] = *(uint4*)v;
    }
}

// ---------------- launcher ----------------
extern "C" void kernel_launch(void* const* d_in, const int* in_sizes, int n_in,
                              void* d_out, int out_size) {
    const float* hidden = (const float*)d_in[0];
    const float* norm_w = (const float*)d_in[1];
    const float* W_in   = (const float*)d_in[2];
    const float* conv_w = (const float*)d_in[3];
    const float* conv_b = (const float*)d_in[4];
    const float* W_x    = (const float*)d_in[5];
    const float* W_dt   = (const float*)d_in[6];
    const float* b_dt   = (const float*)d_in[7];
    const float* A_log  = (const float*)d_in[8];
    const float* D_skip = (const float*)d_in[9];
    const float* W_out  = (const float*)d_in[10];
    float* out = (float*)d_out;

    float *p_xz, *p_xs, *p_dbl, *p_dt, *p_dtT, *p_xsT, *p_zT;
    bf16 *p_nrmb, *p_xsb, *p_dblb, *p_yb, *p_winb, *p_wxb, *p_wdtb, *p_woutb;
    cudaGetSymbolAddress((void**)&p_xz,   g_xz);
    cudaGetSymbolAddress((void**)&p_xs,   g_xs);
    cudaGetSymbolAddress((void**)&p_dbl,  g_dbl);
    cudaGetSymbolAddress((void**)&p_dt,   g_dt);
    cudaGetSymbolAddress((void**)&p_dtT,  g_dtT);
    cudaGetSymbolAddress((void**)&p_xsT,  g_xsT);
    cudaGetSymbolAddress((void**)&p_zT,   g_zT);
    cudaGetSymbolAddress((void**)&p_nrmb, g_nrmb);
    cudaGetSymbolAddress((void**)&p_xsb,  g_xsb);
    cudaGetSymbolAddress((void**)&p_dblb, g_dblb);
    cudaGetSymbolAddress((void**)&p_yb,   g_yb);
    cudaGetSymbolAddress((void**)&p_winb, g_winb);
    cudaGetSymbolAddress((void**)&p_wxb,  g_wxb);
    cudaGetSymbolAddress((void**)&p_wdtb, g_wdtb);
    cudaGetSymbolAddress((void**)&p_woutb, g_woutb);

    // 0) weight conversion to bf16
    f2bf_kernel<<<(DDIM * 2 * EDIM / 4 + 255) / 256, 256>>>(W_in,  p_winb,  DDIM * 2 * EDIM);
    f2bf_kernel<<<(EDIM * 64 / 4 + 255) / 256, 256>>>(W_x,   p_wxb,   EDIM * 64);
    f2bf_kernel<<<(RRANK * EDIM / 4 + 255) / 256, 256>>>(W_dt, p_wdtb, RRANK * EDIM);
    f2bf_kernel<<<(EDIM * DDIM / 4 + 255) / 256, 256>>>(W_out, p_woutb, EDIM * DDIM);

    // 1) RMSNorm -> bf16
    rmsnorm_kernel<<<NTOK, 128>>>(hidden, norm_w, p_nrmb);

    // 2) xz = nrm @ W_in : (8192x512)x(512x2048) -> fp32
    gemm_bf16<128, 128, 2, 4, 0><<<dim3(2 * EDIM / 128, NTOK / 128), 256>>>(
        p_nrmb, DDIM, p_winb, 2 * EDIM, p_xz, 2 * EDIM,
        NTOK, 2 * EDIM, DDIM, nullptr, nullptr, nullptr);

    // 3) conv + silu -> fp32 + bf16 ; z transpose
    conv_silu_kernel<<<dim3(EDIM / 256, LSEQ / 16, BSZ), 256>>>(p_xz, conv_w, conv_b, p_xs, p_xsb);
    transpose_kernel<<<dim3(LSEQ / 32, EDIM / 32, BSZ), dim3(32, 8)>>>(
        p_xz, 2 * EDIM, EDIM, p_zT);
    transpose_kernel<<<dim3(LSEQ / 32, EDIM / 32, BSZ), dim3(32, 8)>>>(
        p_xs, EDIM, 0, p_xsT);

    // 4) dbl = xs @ W_x : (8192x1024)x(1024x64) -> fp32 + bf16
    gemm_bf16<128, 64, 4, 2, 3><<<dim3(1, NTOK / 128), 256>>>(
        p_xsb, EDIM, p_wxb, 64, p_dbl, 64,
        NTOK, 64, EDIM, nullptr, nullptr, p_dblb);

    // 5) dt = softplus(dbl[:, :32] @ W_dt + b_dt) -> fp32 ; transpose
    gemm_bf16<128, 128, 2, 4, 1><<<dim3(EDIM / 128, NTOK / 128), 256>>>(
        p_dblb, 64, p_wdtb, EDIM, p_dt, EDIM,
        NTOK, EDIM, RRANK, b_dt, nullptr, nullptr);
    transpose_kernel<<<dim3(LSEQ / 32, EDIM / 32, BSZ), dim3(32, 8)>>>(
        p_dt, EDIM, 0, p_dtT);

    // 6) chunked parallel scan + gate -> bf16 y
    scan_kernel<<<dim3(EDIM / 8, BSZ), 256>>>(p_dtT, p_xsT, p_zT, p_dbl, A_log, D_skip, p_yb);

    // 7) out = y @ W_out + hidden : (8192x1024)x(1024x512) -> fp32
    gemm_bf16<128, 128, 2, 4, 2><<<dim3(DDIM / 128, NTOK / 128), 256>>>(
        p_yb, EDIM, p_woutb, DDIM, out, DDIM,
        NTOK, DDIM, EDIM, nullptr, hidden, nullptr);
}